// round 3
// baseline (speedup 1.0000x reference)
// LSTM cell fused GEMM on sm_103 *baseline* ISA (no tcgen05 — ptxas target lacks
// the 'a' feature suffix): mma.sync.m16n8k8.tf32 + ldmatrix + cp.async pipeline.
//
// gates[g] = x @ Wx[g]^T + h @ Wh[g]^T + bx[g] + bh[g]   (g = i, f, o, c~)
// c_new = sigm(f)*c + sigm(i)*tanh(c~);  h_new = sigm(o)*tanh(c_new)
//
// Per CTA: 128 batch x (4 gates x 32 feat) = 128x128 tile, all four gates
// resident -> fully fused epilogue via smem regather. K = 4096 (x then h),
// staged 32 floats at a time, 3-stage cp.async pipeline (96 KB, 2 CTA/SM).

#include <cuda_runtime.h>
#include <cstdint>

#define DEVINL __device__ __forceinline__

constexpr int BATCH = 4096;
constexpr int SZ    = 2048;
constexpr int TM    = 128;               // batch tile
constexpr int TOG   = 32;                // per-gate feature tile
constexpr int TN    = 128;               // 4 gates * TOG
constexpr int KS    = 32;                // K per stage (128 B rows)
constexpr int NS    = (2 * SZ) / KS;     // 128 stages
constexpr int STAGES = 3;
constexpr int ABYTES = TM * KS * 4;      // 16 KB
constexpr int BBYTES = TN * KS * 4;      // 16 KB
constexpr int STAGE_BYTES = ABYTES + BBYTES;       // 32 KB
constexpr int SM_BIAS = STAGES * STAGE_BYTES;      // 98304
constexpr int SMEM_TOTAL = SM_BIAS + TN * 4;       // 98816
constexpr int EPS = 130;                 // epilogue smem row stride (floats)

DEVINL uint32_t smem_u32(const void* p) {
  uint32_t r;
  asm("{ .reg .u64 t; cvta.to.shared.u64 t, %1; cvt.u32.u64 %0, t; }"
      : "=r"(r) : "l"(p));
  return r;
}
DEVINL uint32_t swz(uint32_t b) { return b ^ ((b >> 3) & 0x70); }

DEVINL void cp16(uint32_t dst, const void* src) {
  asm volatile("cp.async.cg.shared.global [%0], [%1], 16;"
               :: "r"(dst), "l"(src));
}
DEVINL void cp_commit() { asm volatile("cp.async.commit_group;"); }
template <int N> DEVINL void cp_wait() {
  asm volatile("cp.async.wait_group %0;" :: "n"(N));
}

DEVINL void ldsm4(uint32_t* r, uint32_t addr) {
  asm volatile(
      "ldmatrix.sync.aligned.m8n8.x4.shared.b16 {%0,%1,%2,%3}, [%4];"
      : "=r"(r[0]), "=r"(r[1]), "=r"(r[2]), "=r"(r[3]) : "r"(addr));
}
DEVINL uint32_t f2tf(uint32_t x) {
  uint32_t y;
  asm("cvt.rna.tf32.f32 %0, %1;" : "=r"(y) : "f"(__uint_as_float(x)));
  return y;
}
DEVINL void mma8(float* d, const uint32_t* a, const uint32_t* b) {
  asm volatile(
      "mma.sync.aligned.m16n8k8.row.col.f32.tf32.tf32.f32 "
      "{%0,%1,%2,%3}, {%4,%5,%6,%7}, {%8,%9}, {%0,%1,%2,%3};"
      : "+f"(d[0]), "+f"(d[1]), "+f"(d[2]), "+f"(d[3])
      : "r"(a[0]), "r"(a[1]), "r"(a[2]), "r"(a[3]), "r"(b[0]), "r"(b[1]));
}

DEVINL float sigmoidf_(float x) { return __fdividef(1.f, 1.f + __expf(-x)); }
DEVINL float tanhf_(float x) {
  float a = fabsf(x);
  float e = __expf(-2.f * a);
  return copysignf(__fdividef(1.f - e, 1.f + e), x);
}

__global__ void __launch_bounds__(256, 2)
lstm_kernel(const float* __restrict__ x, const float* __restrict__ h,
            const float* __restrict__ c, const float* __restrict__ Wx,
            const float* __restrict__ bx, const float* __restrict__ Wh,
            const float* __restrict__ bh, float* __restrict__ out) {
  extern __shared__ char smem[];
  const uint32_t sb = smem_u32(smem);
  const int tid = threadIdx.x;
  const int lane = tid & 31;
  const int wid = tid >> 5;
  const int m0 = blockIdx.x * TM;      // batch origin
  const int o0 = blockIdx.y * TOG;     // per-gate feature origin
  const int warp_m = (wid >> 2) * 64;  // 2 warps along M
  const int warp_n = (wid & 3) * 32;   // 4 warps along N

  // Per-CTA bias sums.
  float* bias_sm = (float*)(smem + SM_BIAS);
  for (int i = tid; i < TN; i += 256) {
    int g = i >> 5, o = o0 + (i & 31);
    bias_sm[i] = bx[g * SZ + o] + bh[g * SZ + o];
  }

  // ldmatrix per-lane geometry (tf32: each 8x8 b32 tile = 8 rows x 16 B).
  const int a_r  = lane & 15;                       // A frag row in 16-row tile
  const int a_c4 = (lane & 16) ? 16 : 0;            // byte offset: +4 cols
  const int b_r  = (lane & 7) | ((lane & 16) >> 1); // B frag row (n) in 16
  const int b_c4 = (lane & 8) ? 16 : 0;

  // Stage producer: A = activations [128 x 32], B = weights for 4 gates.
  auto load_stage = [&](int s, int buf) {
    const float* __restrict__ sa = (s < NS / 2) ? x : h;
    const float* __restrict__ sw = (s < NS / 2) ? Wx : Wh;
    const int k0 = (s & (NS / 2 - 1)) * KS;
    const uint32_t ab = sb + buf * STAGE_BYTES;
    const uint32_t bb = ab + ABYTES;
#pragma unroll
    for (int j = 0; j < 4; ++j) {
      int ch = tid + j * 256;
      int row = ch >> 3, cc = ch & 7;
      cp16(ab + swz((uint32_t)(row * 128 + cc * 16)),
           sa + (size_t)(m0 + row) * SZ + (k0 + cc * 4));
    }
#pragma unroll
    for (int j = 0; j < 4; ++j) {
      int ch = tid + j * 256;
      int row = ch >> 3, cc = ch & 7;   // row = g*32 + o_local
      int g = row >> 5, o = row & 31;
      cp16(bb + swz((uint32_t)(row * 128 + cc * 16)),
           sw + (size_t)(g * SZ + o0 + o) * SZ + (k0 + cc * 4));
    }
  };

  float acc[4][4][4];
#pragma unroll
  for (int i = 0; i < 4; ++i)
#pragma unroll
    for (int j = 0; j < 4; ++j)
#pragma unroll
      for (int e = 0; e < 4; ++e) acc[i][j][e] = 0.f;

  // Prologue: fill STAGES-1 buffers.
  load_stage(0, 0); cp_commit();
  load_stage(1, 1); cp_commit();

  for (int s = 0; s < NS; ++s) {
    cp_wait<1>();
    __syncthreads();
    if (s + 2 < NS) load_stage(s + 2, (s + 2) % STAGES);
    cp_commit();

    const uint32_t ab = sb + (s % STAGES) * STAGE_BYTES;
    const uint32_t bb = ab + ABYTES;
#pragma unroll
    for (int ks = 0; ks < 4; ++ks) {
      uint32_t af[4][4], bf[4][2];
#pragma unroll
      for (int mt = 0; mt < 4; ++mt)
        ldsm4(af[mt],
              ab + swz((uint32_t)((warp_m + mt * 16 + a_r) * 128 + ks * 32 + a_c4)));
#pragma unroll
      for (int np = 0; np < 2; ++np) {
        uint32_t t[4];
        ldsm4(t, bb + swz((uint32_t)((warp_n + np * 16 + b_r) * 128 + ks * 32 + b_c4)));
        bf[np * 2][0] = t[0]; bf[np * 2][1] = t[1];
        bf[np * 2 + 1][0] = t[2]; bf[np * 2 + 1][1] = t[3];
      }
#pragma unroll
      for (int mt = 0; mt < 4; ++mt)
#pragma unroll
        for (int e = 0; e < 4; ++e) af[mt][e] = f2tf(af[mt][e]);
#pragma unroll
      for (int nt = 0; nt < 4; ++nt) {
        bf[nt][0] = f2tf(bf[nt][0]);
        bf[nt][1] = f2tf(bf[nt][1]);
      }
#pragma unroll
      for (int mt = 0; mt < 4; ++mt)
#pragma unroll
        for (int nt = 0; nt < 4; ++nt) mma8(acc[mt][nt], af[mt], bf[nt]);
    }
  }

  // Epilogue: regather all 4 gates per (b, o) through smem (reuse stage bufs).
  cp_wait<0>();
  __syncthreads();
  float* ep = (float*)smem;  // [128][EPS]
#pragma unroll
  for (int mt = 0; mt < 4; ++mt)
#pragma unroll
    for (int nt = 0; nt < 4; ++nt) {
      int row = warp_m + mt * 16 + (lane >> 2);
      int col = warp_n + nt * 8 + 2 * (lane & 3);
      ep[row * EPS + col]           = acc[mt][nt][0];
      ep[row * EPS + col + 1]       = acc[mt][nt][1];
      ep[(row + 8) * EPS + col]     = acc[mt][nt][2];
      ep[(row + 8) * EPS + col + 1] = acc[mt][nt][3];
    }
  __syncthreads();

#pragma unroll 1
  for (int p = 0; p < 16; ++p) {
    int idx = tid + p * 256;       // 128*32 = 4096 outputs per CTA
    int b = idx >> 5, o = idx & 31;
    float gi = ep[b * EPS + 0 * 32 + o] + bias_sm[0 * 32 + o];
    float gf = ep[b * EPS + 1 * 32 + o] + bias_sm[1 * 32 + o];
    float go = ep[b * EPS + 2 * 32 + o] + bias_sm[2 * 32 + o];
    float gc = ep[b * EPS + 3 * 32 + o] + bias_sm[3 * 32 + o];
    size_t gidx = (size_t)(m0 + b) * SZ + (o0 + o);
    float cv = c[gidx];
    float iv = sigmoidf_(gi), fv = sigmoidf_(gf), ov = sigmoidf_(go);
    float cand = tanhf_(gc);
    float cn = fv * cv + iv * cand;
    out[gidx] = ov * tanhf_(cn);
    out[(size_t)BATCH * SZ + gidx] = cn;
  }
}

extern "C" void kernel_launch(void* const* d_in, const int* in_sizes, int n_in,
                              void* d_out, int out_size) {
  (void)in_sizes; (void)n_in; (void)out_size;
  const float* x  = (const float*)d_in[0];
  const float* h  = (const float*)d_in[1];
  const float* c  = (const float*)d_in[2];
  const float* Wx = (const float*)d_in[3];
  const float* bx = (const float*)d_in[4];
  const float* Wh = (const float*)d_in[5];
  const float* bh = (const float*)d_in[6];
  cudaFuncSetAttribute(lstm_kernel, cudaFuncAttributeMaxDynamicSharedMemorySize,
                       SMEM_TOTAL);
  dim3 grid(BATCH / TM, SZ / TOG, 1);
  lstm_kernel<<<grid, 256, SMEM_TOTAL>>>(x, h, c, Wx, bx, Wh, bh, (float*)d_out);
}

// round 4
// speedup vs baseline: 2.2329x; 2.2329x over previous
// LSTM cell fused GEMM on sm_103 baseline ISA, fp16 mma.sync.m16n8k16.
//
// Phase 1 (4 small kernels): convert x, h, Wx, Wh fp32 -> fp16 into a
//   __device__ scratch (96 MB). ~45 us, amortized: every weight element is
//   then read 32x as fp16 instead of being cvt'd per-use in the mainloop.
// Phase 2 (GEMM kernel): per CTA 128 batch x (4 gates x 32 feat) output tile,
//   all four gates resident -> fully fused LSTM epilogue. K = 4096 (x then h),
//   64-half K stages, 3-stage cp.async pipeline (96 KB smem, 2 CTA/SM).
//   fp32 accumulation; zero conversion instructions in the mainloop.

#include <cuda_runtime.h>
#include <cuda_fp16.h>
#include <cstdint>

#define DEVINL __device__ __forceinline__

constexpr int BATCH = 4096;
constexpr int SZ    = 2048;
constexpr int TM    = 128;               // batch tile
constexpr int TOG   = 32;                // per-gate feature tile
constexpr int TN    = 128;               // 4 gates * TOG
constexpr int KS    = 64;                // K halfs per stage (128 B rows)
constexpr int NS    = (2 * SZ) / KS;     // 64 stages
constexpr int STAGES = 3;
constexpr int ABYTES = TM * KS * 2;      // 16 KB
constexpr int BBYTES = TN * KS * 2;      // 16 KB
constexpr int STAGE_BYTES = ABYTES + BBYTES;   // 32 KB
constexpr int SM_BIAS = STAGES * STAGE_BYTES;  // 98304
constexpr int SMEM_TOTAL = SM_BIAS + TN * 4;   // 98816
constexpr int EPS = 130;                 // epilogue smem row stride (floats)

// fp16 scratch: [x | h | Wx | Wh]
constexpr size_t OFF_X  = 0;
constexpr size_t OFF_H  = (size_t)BATCH * SZ;            //  8,388,608
constexpr size_t OFF_WX = OFF_H + (size_t)BATCH * SZ;    // 16,777,216
constexpr size_t OFF_WH = OFF_WX + (size_t)4 * SZ * SZ;  // 33,554,432
constexpr size_t SCRATCH_ELEMS = OFF_WH + (size_t)4 * SZ * SZ;  // 50,331,648
__device__ __half g_scratch[SCRATCH_ELEMS];

DEVINL uint32_t smem_u32(const void* p) {
  uint32_t r;
  asm("{ .reg .u64 t; cvta.to.shared.u64 t, %1; cvt.u32.u64 %0, t; }"
      : "=r"(r) : "l"(p));
  return r;
}
DEVINL uint32_t swz(uint32_t b) { return b ^ ((b >> 3) & 0x70); }

DEVINL void cp16(uint32_t dst, const void* src) {
  asm volatile("cp.async.cg.shared.global [%0], [%1], 16;"
               :: "r"(dst), "l"(src));
}
DEVINL void cp_commit() { asm volatile("cp.async.commit_group;"); }
template <int N> DEVINL void cp_wait() {
  asm volatile("cp.async.wait_group %0;" :: "n"(N));
}

DEVINL void ldsm4(uint32_t* r, uint32_t addr) {
  asm volatile(
      "ldmatrix.sync.aligned.m8n8.x4.shared.b16 {%0,%1,%2,%3}, [%4];"
      : "=r"(r[0]), "=r"(r[1]), "=r"(r[2]), "=r"(r[3]) : "r"(addr));
}
DEVINL void mma16(float* d, const uint32_t* a, const uint32_t* b) {
  asm volatile(
      "mma.sync.aligned.m16n8k16.row.col.f32.f16.f16.f32 "
      "{%0,%1,%2,%3}, {%4,%5,%6,%7}, {%8,%9}, {%0,%1,%2,%3};"
      : "+f"(d[0]), "+f"(d[1]), "+f"(d[2]), "+f"(d[3])
      : "r"(a[0]), "r"(a[1]), "r"(a[2]), "r"(a[3]), "r"(b[0]), "r"(b[1]));
}

DEVINL float sigmoidf_(float x) { return __fdividef(1.f, 1.f + __expf(-x)); }
DEVINL float tanhf_(float x) {
  float a = fabsf(x);
  float e = __expf(-2.f * a);
  return copysignf(__fdividef(1.f - e, 1.f + e), x);
}

// ---- Phase 1: fp32 -> fp16 converter (vectorized, exact grid) ----
__global__ void __launch_bounds__(256)
cvt_kernel(const float* __restrict__ src, size_t dst_off, int n4) {
  int i = blockIdx.x * 256 + threadIdx.x;
  if (i < n4) {
    float4 v = ((const float4*)src)[i];
    __half2* dst = (__half2*)(g_scratch + dst_off);
    dst[2 * i]     = __floats2half2_rn(v.x, v.y);
    dst[2 * i + 1] = __floats2half2_rn(v.z, v.w);
  }
}

// ---- Phase 2: fused GEMM + LSTM epilogue ----
__global__ void __launch_bounds__(256, 2)
lstm_kernel(const float* __restrict__ c, const float* __restrict__ bx,
            const float* __restrict__ bh, float* __restrict__ out) {
  extern __shared__ char smem[];
  const uint32_t sb = smem_u32(smem);
  const int tid = threadIdx.x;
  const int lane = tid & 31;
  const int wid = tid >> 5;
  const int m0 = blockIdx.x * TM;      // batch origin
  const int o0 = blockIdx.y * TOG;     // per-gate feature origin
  const int warp_m = (wid >> 2) * 64;  // 2 warps along M
  const int warp_n = (wid & 3) * 32;   // 4 warps along N

  float* bias_sm = (float*)(smem + SM_BIAS);
  for (int i = tid; i < TN; i += 256) {
    int g = i >> 5, o = o0 + (i & 31);
    bias_sm[i] = bx[g * SZ + o] + bh[g * SZ + o];
  }

  // ldmatrix lane geometry (b16 tiles; rows are 128 B, 16 B chunks).
  const int a_r  = lane & 15;                        // A rows m0..15
  const int a_c  = (lane & 16) ? 16 : 0;             // +16 B = k+8
  const int b_r  = (lane & 7) | ((lane & 16) >> 1);  // B rows n0..15
  const int b_c  = (lane & 8) ? 16 : 0;              // +16 B = k+8

  auto load_stage = [&](int s, int buf) {
    const __half* __restrict__ sa =
        g_scratch + ((s < NS / 2) ? OFF_X : OFF_H);
    const __half* __restrict__ sw =
        g_scratch + ((s < NS / 2) ? OFF_WX : OFF_WH);
    const int k0 = (s & (NS / 2 - 1)) * KS;
    const uint32_t ab = sb + buf * STAGE_BYTES;
    const uint32_t bb = ab + ABYTES;
#pragma unroll
    for (int j = 0; j < 4; ++j) {     // A: 128 rows x 128 B = 1024 chunks
      int ch = tid + j * 256;
      int row = ch >> 3, cc = ch & 7;
      cp16(ab + swz((uint32_t)(row * 128 + cc * 16)),
           sa + (size_t)(m0 + row) * SZ + (k0 + cc * 8));
    }
#pragma unroll
    for (int j = 0; j < 4; ++j) {     // B: rows = g*32 + o_local
      int ch = tid + j * 256;
      int row = ch >> 3, cc = ch & 7;
      int g = row >> 5, o = row & 31;
      cp16(bb + swz((uint32_t)(row * 128 + cc * 16)),
           sw + (size_t)(g * SZ + o0 + o) * SZ + (k0 + cc * 8));
    }
  };

  float acc[4][4][4];
#pragma unroll
  for (int i = 0; i < 4; ++i)
#pragma unroll
    for (int j = 0; j < 4; ++j)
#pragma unroll
      for (int e = 0; e < 4; ++e) acc[i][j][e] = 0.f;

  load_stage(0, 0); cp_commit();
  load_stage(1, 1); cp_commit();

  for (int s = 0; s < NS; ++s) {
    cp_wait<1>();
    __syncthreads();
    if (s + 2 < NS) load_stage(s + 2, (s + 2) % STAGES);
    cp_commit();

    const uint32_t ab = sb + (s % STAGES) * STAGE_BYTES;
    const uint32_t bb = ab + ABYTES;
#pragma unroll
    for (int ks = 0; ks < 4; ++ks) {   // 4 x k16 = 64 halfs
      uint32_t af[4][4], bq[2][4];
#pragma unroll
      for (int mt = 0; mt < 4; ++mt)
        ldsm4(af[mt],
              ab + swz((uint32_t)((warp_m + mt * 16 + a_r) * 128 + ks * 32 + a_c)));
#pragma unroll
      for (int np = 0; np < 2; ++np)
        ldsm4(bq[np],
              bb + swz((uint32_t)((warp_n + np * 16 + b_r) * 128 + ks * 32 + b_c)));
#pragma unroll
      for (int mt = 0; mt < 4; ++mt)
#pragma unroll
        for (int nt = 0; nt < 4; ++nt)
          mma16(acc[mt][nt], af[mt], &bq[nt >> 1][(nt & 1) * 2]);
    }
  }

  // Epilogue: regather all 4 gates per (b, o) through smem (reuse stage bufs).
  cp_wait<0>();
  __syncthreads();
  float* ep = (float*)smem;  // [128][EPS]
#pragma unroll
  for (int mt = 0; mt < 4; ++mt)
#pragma unroll
    for (int nt = 0; nt < 4; ++nt) {
      int row = warp_m + mt * 16 + (lane >> 2);
      int col = warp_n + nt * 8 + 2 * (lane & 3);
      ep[row * EPS + col]           = acc[mt][nt][0];
      ep[row * EPS + col + 1]       = acc[mt][nt][1];
      ep[(row + 8) * EPS + col]     = acc[mt][nt][2];
      ep[(row + 8) * EPS + col + 1] = acc[mt][nt][3];
    }
  __syncthreads();

#pragma unroll 1
  for (int p = 0; p < 16; ++p) {
    int idx = tid + p * 256;          // 128*32 outputs per CTA
    int b = idx >> 5, o = idx & 31;
    float gi = ep[b * EPS + 0 * 32 + o] + bias_sm[0 * 32 + o];
    float gf = ep[b * EPS + 1 * 32 + o] + bias_sm[1 * 32 + o];
    float go = ep[b * EPS + 2 * 32 + o] + bias_sm[2 * 32 + o];
    float gc = ep[b * EPS + 3 * 32 + o] + bias_sm[3 * 32 + o];
    size_t gidx = (size_t)(m0 + b) * SZ + (o0 + o);
    float cv = c[gidx];
    float iv = sigmoidf_(gi), fv = sigmoidf_(gf), ov = sigmoidf_(go);
    float cand = tanhf_(gc);
    float cn = fv * cv + iv * cand;
    out[gidx] = ov * tanhf_(cn);
    out[(size_t)BATCH * SZ + gidx] = cn;
  }
}

extern "C" void kernel_launch(void* const* d_in, const int* in_sizes, int n_in,
                              void* d_out, int out_size) {
  (void)in_sizes; (void)n_in; (void)out_size;
  const float* x  = (const float*)d_in[0];
  const float* h  = (const float*)d_in[1];
  const float* c  = (const float*)d_in[2];
  const float* Wx = (const float*)d_in[3];
  const float* bx = (const float*)d_in[4];
  const float* Wh = (const float*)d_in[5];
  const float* bh = (const float*)d_in[6];

  const int act4 = BATCH * SZ / 4;     // 2,097,152
  const int w4   = 4 * SZ * SZ / 4;    // 4,194,304
  cvt_kernel<<<act4 / 256, 256>>>(x,  OFF_X,  act4);
  cvt_kernel<<<act4 / 256, 256>>>(h,  OFF_H,  act4);
  cvt_kernel<<<w4 / 256,   256>>>(Wx, OFF_WX, w4);
  cvt_kernel<<<w4 / 256,   256>>>(Wh, OFF_WH, w4);

  cudaFuncSetAttribute(lstm_kernel, cudaFuncAttributeMaxDynamicSharedMemorySize,
                       SMEM_TOTAL);
  dim3 grid(BATCH / TM, SZ / TOG, 1);
  lstm_kernel<<<grid, 256, SMEM_TOTAL>>>(c, bx, bh, (float*)d_out);
}